// round 1
// baseline (speedup 1.0000x reference)
#include <cuda_runtime.h>
#include <math.h>

#define BATCH 8192
#define NVRT  778
#define NJO   21
#define NF    135
#define NM    336      /* 21*16 */
#define NN    1008     /* NM*3  */
#define NNP   1024
#define NFC   405      /* NF*3  */
#define PPLD  784

// ---------------- scratch (__device__ globals; zero-init at load; padding never written) ----
__device__ float g_vsh[NVRT * 3];
__device__ float g_Jk[48];
__device__ float g_W2[NVRT * NM];
__device__ float g_Pp[NFC * PPLD];
__device__ float g_M[NM];
__device__ float g_C0[NNP];          // [1008..1024) stays 0
__device__ float g_D[NF * NNP];      // n in [1008..1024) stays 0
__device__ float g_pf[BATCH * NF];
__device__ float g_A[BATCH * 192];   // per batch: 16 joints x (R 9, t 3)

// ---------------- f32x2 helpers ----------------
typedef unsigned long long u64;
__device__ __forceinline__ u64 pk2(float x, float y) {
    u64 r; asm("mov.b64 %0, {%1, %2};" : "=l"(r) : "f"(x), "f"(y)); return r;
}
__device__ __forceinline__ void upk2(u64 v, float& x, float& y) {
    asm("mov.b64 {%0, %1}, %2;" : "=f"(x), "=f"(y) : "l"(v));
}
__device__ __forceinline__ u64 fma2(u64 a, u64 b, u64 c) {
    u64 d; asm("fma.rn.f32x2 %0, %1, %2, %3;" : "=l"(d) : "l"(a), "l"(b), "l"(c)); return d;
}

// ---------------- precompute kernels ----------------
__global__ void k_vsh(const float* __restrict__ us, const float* __restrict__ sd,
                      const float* __restrict__ vt) {
    int idx = blockIdx.x * blockDim.x + threadIdx.x;
    if (idx >= NVRT * 3) return;
    float s = vt[idx];
#pragma unroll
    for (int i = 0; i < 10; i++) s += us[i] * sd[i * 2334 + idx];
    g_vsh[idx] = s;
}

__global__ void k_Jk(const float* __restrict__ Jr) {
    int j = blockIdx.x / 3, c = blockIdx.x % 3;
    int t = threadIdx.x;
    float s = 0.f;
    for (int v = t; v < NVRT; v += 128) s += g_vsh[v * 3 + c] * Jr[v * 21 + j];
    __shared__ float red[128];
    red[t] = s; __syncthreads();
    for (int o = 64; o > 0; o >>= 1) { if (t < o) red[t] += red[t + o]; __syncthreads(); }
    if (t == 0) g_Jk[j * 3 + c] = red[0];
}

__global__ void k_W2(const float* __restrict__ Jr, const float* __restrict__ wg) {
    int idx = blockIdx.x * blockDim.x + threadIdx.x;
    if (idx >= NVRT * NM) return;
    int v = idx / NM, m = idx - v * NM;
    int jo = m >> 4, j = m & 15;
    g_W2[idx] = Jr[v * 21 + jo] * wg[v * 16 + j];
}

__global__ void k_MC0() {
    int m = blockIdx.x, t = threadIdx.x;
    float sm = 0.f, s0 = 0.f, s1 = 0.f, s2 = 0.f;
    for (int v = t; v < NVRT; v += 128) {
        float w = g_W2[v * NM + m];
        sm += w;
        s0 += w * g_vsh[v * 3 + 0];
        s1 += w * g_vsh[v * 3 + 1];
        s2 += w * g_vsh[v * 3 + 2];
    }
    __shared__ float red[4][128];
    red[0][t] = sm; red[1][t] = s0; red[2][t] = s1; red[3][t] = s2;
    __syncthreads();
    for (int o = 64; o > 0; o >>= 1) {
        if (t < o) {
            red[0][t] += red[0][t + o]; red[1][t] += red[1][t + o];
            red[2][t] += red[2][t + o]; red[3][t] += red[3][t + o];
        }
        __syncthreads();
    }
    if (t == 0) {
        g_M[m] = red[0][0];
        g_C0[m * 3 + 0] = red[1][0];
        g_C0[m * 3 + 1] = red[2][0];
        g_C0[m * 3 + 2] = red[3][0];
    }
}

__global__ void k_Pp(const float* __restrict__ pd) {
    int idx = blockIdx.x * blockDim.x + threadIdx.x;
    if (idx >= NFC * NVRT) return;
    int fc = idx / NVRT, v = idx - fc * NVRT;
    int f = fc / 3, c = fc - 3 * f;
    g_Pp[fc * PPLD + v] = pd[f * 2334 + 3 * v + c];
}

// D[fc][m] = sum_v Pp[fc][v] * W2[v][m];  tiles 64(fc) x 32(m), micro 4x2, K-chunk 16
__global__ void k_D() {
    __shared__ float As[64][17];
    __shared__ float Bs[16][32];
    int t = threadIdx.x;
    int tx = t & 15, ty = t >> 4;
    int m0 = blockIdx.x * 32, fc0 = blockIdx.y * 64;
    float acc[4][2] = {};
    for (int k0 = 0; k0 < NVRT; k0 += 16) {
#pragma unroll
        for (int r = 0; r < 4; r++) {
            int e = t + 256 * r; int kk = e & 15, fl = e >> 4;
            int fc = fc0 + fl, k = k0 + kk;
            As[fl][kk] = (fc < NFC && k < NVRT) ? g_Pp[fc * PPLD + k] : 0.f;
        }
#pragma unroll
        for (int r = 0; r < 2; r++) {
            int e = t + 256 * r; int ml = e & 31, kk = e >> 5;
            int m = m0 + ml, k = k0 + kk;
            Bs[kk][ml] = (m < NM && k < NVRT) ? g_W2[k * NM + m] : 0.f;
        }
        __syncthreads();
#pragma unroll
        for (int kk = 0; kk < 16; kk++) {
            float a0 = As[ty * 4 + 0][kk];
            float a1 = As[ty * 4 + 1][kk];
            float a2 = As[ty * 4 + 2][kk];
            float a3 = As[ty * 4 + 3][kk];
            float2 bb = *(const float2*)&Bs[kk][tx * 2];
            acc[0][0] += a0 * bb.x; acc[0][1] += a0 * bb.y;
            acc[1][0] += a1 * bb.x; acc[1][1] += a1 * bb.y;
            acc[2][0] += a2 * bb.x; acc[2][1] += a2 * bb.y;
            acc[3][0] += a3 * bb.x; acc[3][1] += a3 * bb.y;
        }
        __syncthreads();
    }
#pragma unroll
    for (int i = 0; i < 4; i++) {
        int fc = fc0 + ty * 4 + i;
        if (fc >= NFC) continue;
        int f = fc / 3, c = fc - 3 * f;
#pragma unroll
        for (int jj = 0; jj < 2; jj++) {
            int m = m0 + tx * 2 + jj;
            if (m < NM) g_D[f * NNP + m * 3 + c] = acc[i][jj];
        }
    }
}

// ---------------- per-batch kernels ----------------
__global__ void k_pf(const float* __restrict__ theta) {
    int idx = blockIdx.x * blockDim.x + threadIdx.x;
    if (idx >= BATCH * 15) return;
    int b = idx / 15, i = idx - b * 15;
    const float* th = theta + b * 45 + 3 * i;
    float tx = th[0], ty = th[1], tz = th[2];
    float ax = tx + 1e-8f, ay = ty + 1e-8f, az = tz + 1e-8f;
    float angle = sqrtf(ax * ax + ay * ay + az * az);
    float inv = 1.0f / angle;
    float nx = tx * inv, ny = ty * inv, nz = tz * inv;
    float half = 0.5f * angle;
    float sh, ch;
    sincosf(half, &sh, &ch);
    float qw = ch, qx = sh * nx, qy = sh * ny, qz = sh * nz;
    float qn = rsqrtf(qw * qw + qx * qx + qy * qy + qz * qz);
    qw *= qn; qx *= qn; qy *= qn; qz *= qn;
    float w2 = qw * qw, x2 = qx * qx, y2 = qy * qy, z2 = qz * qz;
    float wx = qw * qx, wy = qw * qy, wz = qw * qz;
    float xy = qx * qy, xz = qx * qz, yz = qy * qz;
    float* o = g_pf + b * NF + 9 * i;
    o[0] = w2 + x2 - y2 - z2 - 1.0f;
    o[1] = 2.f * (xy - wz);
    o[2] = 2.f * (wy + xz);
    o[3] = 2.f * (wz + xy);
    o[4] = w2 - x2 + y2 - z2 - 1.0f;
    o[5] = 2.f * (yz - wx);
    o[6] = 2.f * (xz - wy);
    o[7] = 2.f * (wx + yz);
    o[8] = w2 - x2 - y2 + z2 - 1.0f;
}

__global__ void k_chain(const float* __restrict__ dq, const float* __restrict__ iq) {
    int b = blockIdx.x * blockDim.x + threadIdx.x;
    if (b >= BATCH) return;
    float w1 = dq[b * 4 + 0], x1 = dq[b * 4 + 1], y1 = dq[b * 4 + 2], z1 = dq[b * 4 + 3];
    float w2 = iq[0], x2 = iq[1], y2 = iq[2], z2 = iq[3];
    float qw = w1 * w2 - x1 * x2 - y1 * y2 - z1 * z2;
    float qx = w1 * x2 + x1 * w2 + y1 * z2 - z1 * y2;
    float qy = w1 * y2 - x1 * z2 + y1 * w2 + z1 * x2;
    float qz = w1 * z2 + x1 * y2 - y1 * x2 + z1 * w2;
    float qn = rsqrtf(qw * qw + qx * qx + qy * qy + qz * qz);
    qw *= qn; qx *= qn; qy *= qn; qz *= qn;
    float W2_ = qw * qw, X2 = qx * qx, Y2 = qy * qy, Z2 = qz * qz;
    float WX = qw * qx, WY = qw * qy, WZ = qw * qz;
    float XY = qx * qy, XZ = qx * qz, YZ = qy * qz;
    float rr[9], rt[3];
    rr[0] = W2_ + X2 - Y2 - Z2; rr[1] = 2.f * (XY - WZ);       rr[2] = 2.f * (WY + XZ);
    rr[3] = 2.f * (WZ + XY);    rr[4] = W2_ - X2 + Y2 - Z2;    rr[5] = 2.f * (YZ - WX);
    rr[6] = 2.f * (XZ - WY);    rr[7] = 2.f * (WX + YZ);       rr[8] = W2_ - X2 - Y2 + Z2;
    rt[0] = g_Jk[0]; rt[1] = g_Jk[1]; rt[2] = g_Jk[2];
    float* Ao = g_A + b * 192;
    {
        float jx = g_Jk[0], jy = g_Jk[1], jz = g_Jk[2];
#pragma unroll
        for (int k = 0; k < 3; k++) {
            Ao[k * 3 + 0] = rr[k * 3 + 0];
            Ao[k * 3 + 1] = rr[k * 3 + 1];
            Ao[k * 3 + 2] = rr[k * 3 + 2];
            Ao[9 + k] = rt[k] - (rr[k * 3] * jx + rr[k * 3 + 1] * jy + rr[k * 3 + 2] * jz);
        }
    }
#pragma unroll
    for (int ch = 0; ch < 5; ch++) {
        float cr[9], ct[3];
#pragma unroll
        for (int e = 0; e < 9; e++) cr[e] = rr[e];
        ct[0] = rt[0]; ct[1] = rt[1]; ct[2] = rt[2];
#pragma unroll
        for (int s = 0; s < 3; s++) {
            int i = ch * 3 + 1 + s;
            int p = (s == 0) ? 0 : (i - 1);
            float Ri[9];
            const float* pfv = g_pf + b * NF + 9 * (i - 1);
#pragma unroll
            for (int e = 0; e < 9; e++)
                Ri[e] = pfv[e] + ((e == 0 || e == 4 || e == 8) ? 1.0f : 0.0f);
            float rx = g_Jk[3 * i + 0] - g_Jk[3 * p + 0];
            float ry = g_Jk[3 * i + 1] - g_Jk[3 * p + 1];
            float rz = g_Jk[3 * i + 2] - g_Jk[3 * p + 2];
            float nr[9], nt[3];
#pragma unroll
            for (int k = 0; k < 3; k++) {
                nr[3 * k + 0] = cr[3 * k] * Ri[0] + cr[3 * k + 1] * Ri[3] + cr[3 * k + 2] * Ri[6];
                nr[3 * k + 1] = cr[3 * k] * Ri[1] + cr[3 * k + 1] * Ri[4] + cr[3 * k + 2] * Ri[7];
                nr[3 * k + 2] = cr[3 * k] * Ri[2] + cr[3 * k + 1] * Ri[5] + cr[3 * k + 2] * Ri[8];
                nt[k] = cr[3 * k] * rx + cr[3 * k + 1] * ry + cr[3 * k + 2] * rz + ct[k];
            }
            float jx = g_Jk[3 * i + 0], jy = g_Jk[3 * i + 1], jz = g_Jk[3 * i + 2];
            float* Aoi = Ao + i * 12;
#pragma unroll
            for (int k = 0; k < 3; k++) {
                Aoi[k * 3 + 0] = nr[3 * k + 0];
                Aoi[k * 3 + 1] = nr[3 * k + 1];
                Aoi[k * 3 + 2] = nr[3 * k + 2];
                Aoi[9 + k] = nt[k] - (nr[3 * k] * jx + nr[3 * k + 1] * jy + nr[3 * k + 2] * jz);
            }
#pragma unroll
            for (int e = 0; e < 9; e++) cr[e] = nr[e];
            ct[0] = nt[0]; ct[1] = nt[1]; ct[2] = nt[2];
        }
    }
}

// ---------------- main GEMM (B x 1008 x 135, f32x2 batch-pairs) + epilogue ----------------
#define SMEM_BYTES 78336
__global__ void k_gemm_epi(const float* __restrict__ trans, float* __restrict__ out) {
    extern __shared__ float smem[];
    int t = threadIdx.x;
    int b0 = blockIdx.x * 16;

    u64* pfs = (u64*)smem;  // [135][8] batch-pairs
    for (int i = t; i < NF * 8; i += 256) {
        int f = i >> 3, bp = i & 7;
        int b = b0 + 2 * bp;
        pfs[f * 8 + bp] = pk2(g_pf[b * NF + f], g_pf[(b + 1) * NF + f]);
    }
    __syncthreads();

    u64 acc[4][8];
#pragma unroll
    for (int k = 0; k < 4; k++) {
        float c0 = g_C0[t + 256 * k];
        u64 cc = pk2(c0, c0);
#pragma unroll
        for (int bp = 0; bp < 8; bp++) acc[k][bp] = cc;
    }

    for (int f = 0; f < NF; f++) {
        u64 d[4];
#pragma unroll
        for (int k = 0; k < 4; k++) {
            float dv = g_D[f * NNP + t + 256 * k];
            d[k] = pk2(dv, dv);
        }
#pragma unroll
        for (int bp = 0; bp < 8; bp++) {
            u64 p = pfs[f * 8 + bp];
#pragma unroll
            for (int k = 0; k < 4; k++) acc[k][bp] = fma2(d[k], p, acc[k][bp]);
        }
    }
    __syncthreads();

    float* Ps = smem;           // 16*1008 floats
    float* As = smem + 16128;   // 16*192
    float* Ms = smem + 19200;   // 336
    float* Ts = smem + 19536;   // 48
#pragma unroll
    for (int k = 0; k < 4; k++) {
        int n = t + 256 * k;
        if (n < NN) {
#pragma unroll
            for (int bp = 0; bp < 8; bp++) {
                float x, y; upk2(acc[k][bp], x, y);
                Ps[(2 * bp) * NN + n] = x;
                Ps[(2 * bp + 1) * NN + n] = y;
            }
        }
    }
    for (int i = t; i < 16 * 192; i += 256) As[i] = g_A[b0 * 192 + i];
    for (int i = t; i < NM; i += 256) Ms[i] = g_M[i];
    if (t < 48) Ts[t] = trans[b0 * 3 + t];
    __syncthreads();

    for (int idx = t; idx < 1008; idx += 256) {
        int bl = idx / 63;
        int r = idx - bl * 63;
        int jo = r / 3;
        int k = r - jo * 3;
        const float* Ab = As + bl * 192;
        const float* Pb = Ps + bl * NN;
        float s = Ts[bl * 3 + k];
#pragma unroll
        for (int j = 0; j < 16; j++) {
            int rb = j * 12 + k * 3;
            int pb = (jo * 16 + j) * 3;
            s += Ab[rb] * Pb[pb] + Ab[rb + 1] * Pb[pb + 1] + Ab[rb + 2] * Pb[pb + 2]
               + Ms[jo * 16 + j] * Ab[j * 12 + 9 + k];
        }
        out[(b0 + bl) * 63 + jo * 3 + k] = s;
    }
}

// ---------------- launcher ----------------
extern "C" void kernel_launch(void* const* d_in, const int* in_sizes, int n_in,
                              void* d_out, int out_size) {
    const float* theta = (const float*)d_in[0];
    const float* dq    = (const float*)d_in[1];
    const float* us    = (const float*)d_in[2];
    const float* iq    = (const float*)d_in[3];
    const float* tr    = (const float*)d_in[4];
    const float* vt    = (const float*)d_in[5];
    const float* sd    = (const float*)d_in[6];
    const float* Jr    = (const float*)d_in[7];
    const float* pd    = (const float*)d_in[8];
    const float* wg    = (const float*)d_in[9];
    float* out = (float*)d_out;

    cudaFuncSetAttribute(k_gemm_epi, cudaFuncAttributeMaxDynamicSharedMemorySize, SMEM_BYTES);

    k_vsh<<<(NVRT * 3 + 255) / 256, 256>>>(us, sd, vt);
    k_W2<<<(NVRT * NM + 255) / 256, 256>>>(Jr, wg);
    k_Jk<<<48, 128>>>(Jr);
    k_MC0<<<NM, 128>>>();
    k_Pp<<<(NFC * NVRT + 255) / 256, 256>>>(pd);
    k_D<<<dim3(11, 7), 256>>>();
    k_pf<<<(BATCH * 15 + 255) / 256, 256>>>(theta);
    k_chain<<<(BATCH + 127) / 128, 128>>>(dq, iq);
    k_gemm_epi<<<BATCH / 16, 256, SMEM_BYTES>>>(tr, out);
}

// round 2
// speedup vs baseline: 1.2394x; 1.2394x over previous
#include <cuda_runtime.h>
#include <math.h>

#define BATCH 8192
#define NVRT  778
#define NJO   21
#define NF    135
#define NM    336      /* 21*16 */
#define NN    1008     /* NM*3  */
#define NNP   1024
#define NFC   405      /* NF*3  */
#define PPLD  784

// ---------------- scratch (__device__ globals; zero-init; padding never written) ----
__device__ float g_vsh[NVRT * 3];
__device__ float g_Jk[64];
__device__ float g_W2T[NM * PPLD];   // [m][v], v-contiguous, rows padded to 784 (tail stays 0)
__device__ float g_Pp[NFC * PPLD];   // [fc][v]
__device__ float g_M[NM];
__device__ float g_C0[NNP];          // [1008..1024) stays 0
__device__ float g_D[NF * NNP];      // n in [1008..1024) stays 0
__device__ float g_pf[BATCH * NF];
__device__ float g_A[BATCH * 192];   // per batch: 16 joints x (R 9, t 3)

// ---------------- f32x2 helpers ----------------
typedef unsigned long long u64;
__device__ __forceinline__ u64 pk2(float x, float y) {
    u64 r; asm("mov.b64 %0, {%1, %2};" : "=l"(r) : "f"(x), "f"(y)); return r;
}
__device__ __forceinline__ void upk2(u64 v, float& x, float& y) {
    asm("mov.b64 {%0, %1}, %2;" : "=f"(x), "=f"(y) : "l"(v));
}
__device__ __forceinline__ u64 fma2(u64 a, u64 b, u64 c) {
    u64 d; asm("fma.rn.f32x2 %0, %1, %2, %3;" : "=l"(d) : "l"(a), "l"(b), "l"(c)); return d;
}

// ---------------- stage 1: vsh + transposed skinning weights W2T ----------------
// 25 blocks, each owns a 32-vertex chunk. All global reads/writes coalesced.
__global__ void k_pre1(const float* __restrict__ us, const float* __restrict__ sd,
                       const float* __restrict__ vt, const float* __restrict__ Jr,
                       const float* __restrict__ wg) {
    __shared__ float jrs[32 * 21];   // Jr rows for chunk
    __shared__ float wgs[32 * 17];   // wg rows, padded to 17 (bank-conflict-free)
    int t = threadIdx.x;
    int v0 = blockIdx.x * 32;
    int nv = NVRT - v0; if (nv > 32) nv = 32;

    // stage Jr rows (contiguous slab)
    for (int i = t; i < nv * 21; i += 256) jrs[i] = Jr[v0 * 21 + i];
    // stage wg rows into padded layout
    for (int i = t; i < nv * 16; i += 256) {
        int vl = i >> 4, j = i & 15;
        wgs[vl * 17 + j] = wg[(v0 + vl) * 16 + j];
    }
    // vsh for this chunk (coalesced sd reads)
    for (int i = t; i < nv * 3; i += 256) {
        int g = v0 * 3 + i;
        float s = vt[g];
#pragma unroll
        for (int q = 0; q < 10; q++) s += us[q] * sd[q * 2334 + g];
        g_vsh[g] = s;
    }
    __syncthreads();

    // W2T[m][v] = Jr[v][m/16] * wg[v][m%16]; v fastest -> coalesced 128B stores
    for (int i = t; i < NM * 32; i += 256) {
        int vl = i & 31, m = i >> 5;
        int v = v0 + vl;
        if (v < NVRT)
            g_W2T[m * PPLD + v] = jrs[vl * 21 + (m >> 4)] * wgs[vl * 17 + (m & 15)];
    }
}

// ---------------- stage 2: Jk + M + C0 (coalesced via W2T) ----------------
__global__ void k_pre2(const float* __restrict__ Jr) {
    __shared__ float vs[NVRT * 3];
    __shared__ float red[4][128];
    int t = threadIdx.x;
    for (int i = t; i < NVRT * 3; i += 128) vs[i] = g_vsh[i];
    __syncthreads();

    int blk = blockIdx.x;
    if (blk < NM) {
        int m = blk;
        float sm = 0.f, s0 = 0.f, s1 = 0.f, s2 = 0.f;
        for (int v = t; v < NVRT; v += 128) {
            float w = g_W2T[m * PPLD + v];      // coalesced
            sm += w;
            s0 += w * vs[v * 3 + 0];
            s1 += w * vs[v * 3 + 1];
            s2 += w * vs[v * 3 + 2];
        }
        red[0][t] = sm; red[1][t] = s0; red[2][t] = s1; red[3][t] = s2;
        __syncthreads();
        for (int o = 64; o > 0; o >>= 1) {
            if (t < o) {
                red[0][t] += red[0][t + o]; red[1][t] += red[1][t + o];
                red[2][t] += red[2][t + o]; red[3][t] += red[3][t + o];
            }
            __syncthreads();
        }
        if (t == 0) {
            g_M[m] = red[0][0];
            g_C0[m * 3 + 0] = red[1][0];
            g_C0[m * 3 + 1] = red[2][0];
            g_C0[m * 3 + 2] = red[3][0];
        }
    } else {
        int idx = blk - NM;          // 0..62
        int j = idx / 3, c = idx - 3 * j;
        float s = 0.f;
        for (int v = t; v < NVRT; v += 128) s += vs[v * 3 + c] * Jr[v * 21 + j];
        red[0][t] = s; __syncthreads();
        for (int o = 64; o > 0; o >>= 1) { if (t < o) red[0][t] += red[0][t + o]; __syncthreads(); }
        if (t == 0) g_Jk[j * 3 + c] = red[0][0];
    }
}

// ---------------- posedirs transpose into [fc][v] ----------------
__global__ void k_Pp(const float* __restrict__ pd) {
    int idx = blockIdx.x * blockDim.x + threadIdx.x;
    if (idx >= NFC * NVRT) return;
    int fc = idx / NVRT, v = idx - fc * NVRT;
    int f = fc / 3, c = fc - 3 * f;
    g_Pp[fc * PPLD + v] = pd[f * 2334 + 3 * v + c];
}

// ---------------- D[fc][m] = sum_v Pp[fc][v] * W2T[m][v] ----------------
// 32x32 tiles, 2x2 micro, K-chunk 32, both operands K-contiguous (coalesced)
__global__ void k_D() {
    __shared__ float As[32][33];
    __shared__ float Bs[32][33];
    int t = threadIdx.x;
    int tx = t & 15, ty = t >> 4;
    int m0 = blockIdx.x * 32, fc0 = blockIdx.y * 32;
    float acc[2][2] = {};
    for (int k0 = 0; k0 < PPLD; k0 += 32) {
#pragma unroll
        for (int r = 0; r < 4; r++) {
            int e = t + 256 * r; int kk = e & 31, fl = e >> 5;
            int fc = fc0 + fl;
            As[fl][kk] = (fc < NFC) ? g_Pp[fc * PPLD + k0 + kk] : 0.f;  // padded tail is 0
        }
#pragma unroll
        for (int r = 0; r < 4; r++) {
            int e = t + 256 * r; int kk = e & 31, ml = e >> 5;
            int m = m0 + ml;
            Bs[ml][kk] = (m < NM) ? g_W2T[m * PPLD + k0 + kk] : 0.f;
        }
        __syncthreads();
#pragma unroll
        for (int kk = 0; kk < 32; kk++) {
            float a0 = As[ty][kk], a1 = As[ty + 16][kk];
            float b0 = Bs[tx][kk], b1 = Bs[tx + 16][kk];
            acc[0][0] += a0 * b0; acc[0][1] += a0 * b1;
            acc[1][0] += a1 * b0; acc[1][1] += a1 * b1;
        }
        __syncthreads();
    }
#pragma unroll
    for (int i = 0; i < 2; i++) {
        int fc = fc0 + ty + 16 * i;
        if (fc >= NFC) continue;
        int f = fc / 3, c = fc - 3 * f;
#pragma unroll
        for (int jj = 0; jj < 2; jj++) {
            int m = m0 + tx + 16 * jj;
            if (m < NM) g_D[f * NNP + m * 3 + c] = acc[i][jj];
        }
    }
}

// ---------------- per-batch: pose features (R - I flattened) ----------------
__global__ void k_pf(const float* __restrict__ theta) {
    int idx = blockIdx.x * blockDim.x + threadIdx.x;
    if (idx >= BATCH * 15) return;
    int b = idx / 15, i = idx - b * 15;
    const float* th = theta + b * 45 + 3 * i;
    float tx = th[0], ty = th[1], tz = th[2];
    float ax = tx + 1e-8f, ay = ty + 1e-8f, az = tz + 1e-8f;
    float angle = sqrtf(ax * ax + ay * ay + az * az);
    float inv = 1.0f / angle;
    float nx = tx * inv, ny = ty * inv, nz = tz * inv;
    float half = 0.5f * angle;
    float sh, ch;
    sincosf(half, &sh, &ch);
    float qw = ch, qx = sh * nx, qy = sh * ny, qz = sh * nz;
    float qn = rsqrtf(qw * qw + qx * qx + qy * qy + qz * qz);
    qw *= qn; qx *= qn; qy *= qn; qz *= qn;
    float w2 = qw * qw, x2 = qx * qx, y2 = qy * qy, z2 = qz * qz;
    float wx = qw * qx, wy = qw * qy, wz = qw * qz;
    float xy = qx * qy, xz = qx * qz, yz = qy * qz;
    float* o = g_pf + b * NF + 9 * i;
    o[0] = w2 + x2 - y2 - z2 - 1.0f;
    o[1] = 2.f * (xy - wz);
    o[2] = 2.f * (wy + xz);
    o[3] = 2.f * (wz + xy);
    o[4] = w2 - x2 + y2 - z2 - 1.0f;
    o[5] = 2.f * (yz - wx);
    o[6] = 2.f * (xz - wy);
    o[7] = 2.f * (wx + yz);
    o[8] = w2 - x2 - y2 + z2 - 1.0f;
}

// ---------------- per-batch: kinematic chain -> A matrices ----------------
__global__ void k_chain(const float* __restrict__ dq, const float* __restrict__ iq) {
    int b = blockIdx.x * blockDim.x + threadIdx.x;
    if (b >= BATCH) return;
    float w1 = dq[b * 4 + 0], x1 = dq[b * 4 + 1], y1 = dq[b * 4 + 2], z1 = dq[b * 4 + 3];
    float w2 = iq[0], x2 = iq[1], y2 = iq[2], z2 = iq[3];
    float qw = w1 * w2 - x1 * x2 - y1 * y2 - z1 * z2;
    float qx = w1 * x2 + x1 * w2 + y1 * z2 - z1 * y2;
    float qy = w1 * y2 - x1 * z2 + y1 * w2 + z1 * x2;
    float qz = w1 * z2 + x1 * y2 - y1 * x2 + z1 * w2;
    float qn = rsqrtf(qw * qw + qx * qx + qy * qy + qz * qz);
    qw *= qn; qx *= qn; qy *= qn; qz *= qn;
    float W2_ = qw * qw, X2 = qx * qx, Y2 = qy * qy, Z2 = qz * qz;
    float WX = qw * qx, WY = qw * qy, WZ = qw * qz;
    float XY = qx * qy, XZ = qx * qz, YZ = qy * qz;
    float rr[9], rt[3];
    rr[0] = W2_ + X2 - Y2 - Z2; rr[1] = 2.f * (XY - WZ);       rr[2] = 2.f * (WY + XZ);
    rr[3] = 2.f * (WZ + XY);    rr[4] = W2_ - X2 + Y2 - Z2;    rr[5] = 2.f * (YZ - WX);
    rr[6] = 2.f * (XZ - WY);    rr[7] = 2.f * (WX + YZ);       rr[8] = W2_ - X2 - Y2 + Z2;
    rt[0] = g_Jk[0]; rt[1] = g_Jk[1]; rt[2] = g_Jk[2];
    float* Ao = g_A + b * 192;
    {
        float jx = g_Jk[0], jy = g_Jk[1], jz = g_Jk[2];
#pragma unroll
        for (int k = 0; k < 3; k++) {
            Ao[k * 3 + 0] = rr[k * 3 + 0];
            Ao[k * 3 + 1] = rr[k * 3 + 1];
            Ao[k * 3 + 2] = rr[k * 3 + 2];
            Ao[9 + k] = rt[k] - (rr[k * 3] * jx + rr[k * 3 + 1] * jy + rr[k * 3 + 2] * jz);
        }
    }
#pragma unroll
    for (int ch = 0; ch < 5; ch++) {
        float cr[9], ct[3];
#pragma unroll
        for (int e = 0; e < 9; e++) cr[e] = rr[e];
        ct[0] = rt[0]; ct[1] = rt[1]; ct[2] = rt[2];
#pragma unroll
        for (int s = 0; s < 3; s++) {
            int i = ch * 3 + 1 + s;
            int p = (s == 0) ? 0 : (i - 1);
            float Ri[9];
            const float* pfv = g_pf + b * NF + 9 * (i - 1);
#pragma unroll
            for (int e = 0; e < 9; e++)
                Ri[e] = pfv[e] + ((e == 0 || e == 4 || e == 8) ? 1.0f : 0.0f);
            float rx = g_Jk[3 * i + 0] - g_Jk[3 * p + 0];
            float ry = g_Jk[3 * i + 1] - g_Jk[3 * p + 1];
            float rz = g_Jk[3 * i + 2] - g_Jk[3 * p + 2];
            float nr[9], nt[3];
#pragma unroll
            for (int k = 0; k < 3; k++) {
                nr[3 * k + 0] = cr[3 * k] * Ri[0] + cr[3 * k + 1] * Ri[3] + cr[3 * k + 2] * Ri[6];
                nr[3 * k + 1] = cr[3 * k] * Ri[1] + cr[3 * k + 1] * Ri[4] + cr[3 * k + 2] * Ri[7];
                nr[3 * k + 2] = cr[3 * k] * Ri[2] + cr[3 * k + 1] * Ri[5] + cr[3 * k + 2] * Ri[8];
                nt[k] = cr[3 * k] * rx + cr[3 * k + 1] * ry + cr[3 * k + 2] * rz + ct[k];
            }
            float jx = g_Jk[3 * i + 0], jy = g_Jk[3 * i + 1], jz = g_Jk[3 * i + 2];
            float* Aoi = Ao + i * 12;
#pragma unroll
            for (int k = 0; k < 3; k++) {
                Aoi[k * 3 + 0] = nr[3 * k + 0];
                Aoi[k * 3 + 1] = nr[3 * k + 1];
                Aoi[k * 3 + 2] = nr[3 * k + 2];
                Aoi[9 + k] = nt[k] - (nr[3 * k] * jx + nr[3 * k + 1] * jy + nr[3 * k + 2] * jz);
            }
#pragma unroll
            for (int e = 0; e < 9; e++) cr[e] = nr[e];
            ct[0] = nt[0]; ct[1] = nt[1]; ct[2] = nt[2];
        }
    }
}

// ---------------- main GEMM (B x 1008 x 135, f32x2 batch-pairs) + epilogue ----------------
#define SMEM_BYTES 78336
__global__ void k_gemm_epi(const float* __restrict__ trans, float* __restrict__ out) {
    extern __shared__ float smem[];
    int t = threadIdx.x;
    int b0 = blockIdx.x * 16;

    u64* pfs = (u64*)smem;  // [135][8] batch-pairs
    for (int i = t; i < NF * 8; i += 256) {
        int f = i >> 3, bp = i & 7;
        int b = b0 + 2 * bp;
        pfs[f * 8 + bp] = pk2(g_pf[b * NF + f], g_pf[(b + 1) * NF + f]);
    }
    __syncthreads();

    u64 acc[4][8];
#pragma unroll
    for (int k = 0; k < 4; k++) {
        float c0 = g_C0[t + 256 * k];
        u64 cc = pk2(c0, c0);
#pragma unroll
        for (int bp = 0; bp < 8; bp++) acc[k][bp] = cc;
    }

    // software-pipelined over f: prefetch next D row while computing current
    float dc[4], dn[4];
#pragma unroll
    for (int k = 0; k < 4; k++) dc[k] = g_D[0 * NNP + t + 256 * k];

    for (int f = 0; f < NF; f++) {
        if (f + 1 < NF) {
#pragma unroll
            for (int k = 0; k < 4; k++) dn[k] = g_D[(f + 1) * NNP + t + 256 * k];
        }
        u64 d2[4];
#pragma unroll
        for (int k = 0; k < 4; k++) d2[k] = pk2(dc[k], dc[k]);
#pragma unroll
        for (int bp = 0; bp < 8; bp++) {
            u64 p = pfs[f * 8 + bp];
#pragma unroll
            for (int k = 0; k < 4; k++) acc[k][bp] = fma2(d2[k], p, acc[k][bp]);
        }
#pragma unroll
        for (int k = 0; k < 4; k++) dc[k] = dn[k];
    }
    __syncthreads();

    float* Ps = smem;           // 16*1008 floats
    float* As = smem + 16128;   // 16*192
    float* Ms = smem + 19200;   // 336
    float* Ts = smem + 19536;   // 48
#pragma unroll
    for (int k = 0; k < 4; k++) {
        int n = t + 256 * k;
        if (n < NN) {
#pragma unroll
            for (int bp = 0; bp < 8; bp++) {
                float x, y; upk2(acc[k][bp], x, y);
                Ps[(2 * bp) * NN + n] = x;
                Ps[(2 * bp + 1) * NN + n] = y;
            }
        }
    }
    for (int i = t; i < 16 * 192; i += 256) As[i] = g_A[b0 * 192 + i];
    for (int i = t; i < NM; i += 256) Ms[i] = g_M[i];
    if (t < 48) Ts[t] = trans[b0 * 3 + t];
    __syncthreads();

    for (int idx = t; idx < 1008; idx += 256) {
        int bl = idx / 63;
        int r = idx - bl * 63;
        int jo = r / 3;
        int k = r - jo * 3;
        const float* Ab = As + bl * 192;
        const float* Pb = Ps + bl * NN;
        float s = Ts[bl * 3 + k];
#pragma unroll
        for (int j = 0; j < 16; j++) {
            int rb = j * 12 + k * 3;
            int pb = (jo * 16 + j) * 3;
            s += Ab[rb] * Pb[pb] + Ab[rb + 1] * Pb[pb + 1] + Ab[rb + 2] * Pb[pb + 2]
               + Ms[jo * 16 + j] * Ab[j * 12 + 9 + k];
        }
        out[(b0 + bl) * 63 + jo * 3 + k] = s;
    }
}

// ---------------- launcher ----------------
extern "C" void kernel_launch(void* const* d_in, const int* in_sizes, int n_in,
                              void* d_out, int out_size) {
    const float* theta = (const float*)d_in[0];
    const float* dq    = (const float*)d_in[1];
    const float* us    = (const float*)d_in[2];
    const float* iq    = (const float*)d_in[3];
    const float* tr    = (const float*)d_in[4];
    const float* vt    = (const float*)d_in[5];
    const float* sd    = (const float*)d_in[6];
    const float* Jr    = (const float*)d_in[7];
    const float* pd    = (const float*)d_in[8];
    const float* wg    = (const float*)d_in[9];
    float* out = (float*)d_out;

    cudaFuncSetAttribute(k_gemm_epi, cudaFuncAttributeMaxDynamicSharedMemorySize, SMEM_BYTES);

    k_pre1<<<25, 256>>>(us, sd, vt, Jr, wg);
    k_Pp<<<(NFC * NVRT + 255) / 256, 256>>>(pd);
    k_pf<<<(BATCH * 15 + 255) / 256, 256>>>(theta);
    k_pre2<<<NM + 63, 128>>>(Jr);
    k_D<<<dim3(11, 13), 256>>>();
    k_chain<<<(BATCH + 127) / 128, 128>>>(dq, iq);
    k_gemm_epi<<<BATCH / 16, 256, SMEM_BYTES>>>(tr, out);
}

// round 3
// speedup vs baseline: 1.6665x; 1.3446x over previous
#include <cuda_runtime.h>
#include <math.h>

#define BATCH 8192
#define NVRT  778
#define NJO   21
#define NF    135
#define NM    336      /* 21*16 */
#define NN    1008     /* NM*3  */
#define NNP   1024
#define NFC   405      /* NF*3  */
#define PPLD  784

// ---------------- scratch (__device__ globals; zero-init; padding never written) ----
__device__ float g_vsh[NVRT * 3];
__device__ float g_Jk[64];
__device__ float g_W2T[NM * PPLD];   // [m][v], v-contiguous, rows padded to 784 (tail stays 0)
__device__ float g_Pp[NFC * PPLD];   // [fc][v]
__device__ float g_M[NM];
__device__ float g_C0[NNP];          // [1008..1024) stays 0
__device__ float g_D[NF * NNP];      // n in [1008..1024) stays 0

// ---------------- f32x2 helpers ----------------
typedef unsigned long long u64;
__device__ __forceinline__ u64 pk2(float x, float y) {
    u64 r; asm("mov.b64 %0, {%1, %2};" : "=l"(r) : "f"(x), "f"(y)); return r;
}
__device__ __forceinline__ void upk2(u64 v, float& x, float& y) {
    asm("mov.b64 {%0, %1}, %2;" : "=f"(x), "=f"(y) : "l"(v));
}
__device__ __forceinline__ u64 fma2(u64 a, u64 b, u64 c) {
    u64 d; asm("fma.rn.f32x2 %0, %1, %2, %3;" : "=l"(d) : "l"(a), "l"(b), "l"(c)); return d;
}

// ---------------- stage 1: vsh + transposed skinning weights W2T ----------------
__global__ void k_pre1(const float* __restrict__ us, const float* __restrict__ sd,
                       const float* __restrict__ vt, const float* __restrict__ Jr,
                       const float* __restrict__ wg) {
    __shared__ float jrs[32 * 21];
    __shared__ float wgs[32 * 17];
    int t = threadIdx.x;
    int v0 = blockIdx.x * 32;
    int nv = NVRT - v0; if (nv > 32) nv = 32;

    for (int i = t; i < nv * 21; i += 256) jrs[i] = Jr[v0 * 21 + i];
    for (int i = t; i < nv * 16; i += 256) {
        int vl = i >> 4, j = i & 15;
        wgs[vl * 17 + j] = wg[(v0 + vl) * 16 + j];
    }
    for (int i = t; i < nv * 3; i += 256) {
        int g = v0 * 3 + i;
        float s = vt[g];
#pragma unroll
        for (int q = 0; q < 10; q++) s += us[q] * sd[q * 2334 + g];
        g_vsh[g] = s;
    }
    __syncthreads();

    for (int i = t; i < NM * 32; i += 256) {
        int vl = i & 31, m = i >> 5;
        int v = v0 + vl;
        if (v < NVRT)
            g_W2T[m * PPLD + v] = jrs[vl * 21 + (m >> 4)] * wgs[vl * 17 + (m & 15)];
    }
}

// ---------------- stage 2: Jk + M + C0 ----------------
__global__ void k_pre2(const float* __restrict__ Jr) {
    __shared__ float vs[NVRT * 3];
    __shared__ float red[4][128];
    int t = threadIdx.x;
    for (int i = t; i < NVRT * 3; i += 128) vs[i] = g_vsh[i];
    __syncthreads();

    int blk = blockIdx.x;
    if (blk < NM) {
        int m = blk;
        float sm = 0.f, s0 = 0.f, s1 = 0.f, s2 = 0.f;
        for (int v = t; v < NVRT; v += 128) {
            float w = g_W2T[m * PPLD + v];
            sm += w;
            s0 += w * vs[v * 3 + 0];
            s1 += w * vs[v * 3 + 1];
            s2 += w * vs[v * 3 + 2];
        }
        red[0][t] = sm; red[1][t] = s0; red[2][t] = s1; red[3][t] = s2;
        __syncthreads();
        for (int o = 64; o > 0; o >>= 1) {
            if (t < o) {
                red[0][t] += red[0][t + o]; red[1][t] += red[1][t + o];
                red[2][t] += red[2][t + o]; red[3][t] += red[3][t + o];
            }
            __syncthreads();
        }
        if (t == 0) {
            g_M[m] = red[0][0];
            g_C0[m * 3 + 0] = red[1][0];
            g_C0[m * 3 + 1] = red[2][0];
            g_C0[m * 3 + 2] = red[3][0];
        }
    } else {
        int idx = blk - NM;
        int j = idx / 3, c = idx - 3 * j;
        float s = 0.f;
        for (int v = t; v < NVRT; v += 128) s += vs[v * 3 + c] * Jr[v * 21 + j];
        red[0][t] = s; __syncthreads();
        for (int o = 64; o > 0; o >>= 1) { if (t < o) red[0][t] += red[0][t + o]; __syncthreads(); }
        if (t == 0) g_Jk[j * 3 + c] = red[0][0];
    }
}

// ---------------- posedirs transpose into [fc][v] ----------------
__global__ void k_Pp(const float* __restrict__ pd) {
    int idx = blockIdx.x * blockDim.x + threadIdx.x;
    if (idx >= NFC * NVRT) return;
    int fc = idx / NVRT, v = idx - fc * NVRT;
    int f = fc / 3, c = fc - 3 * f;
    g_Pp[fc * PPLD + v] = pd[f * 2334 + 3 * v + c];
}

// ---------------- D[fc][m] = sum_v Pp[fc][v] * W2T[m][v] ----------------
__global__ void k_D() {
    __shared__ float As[32][33];
    __shared__ float Bs[32][33];
    int t = threadIdx.x;
    int tx = t & 15, ty = t >> 4;
    int m0 = blockIdx.x * 32, fc0 = blockIdx.y * 32;
    float acc[2][2] = {};
    for (int k0 = 0; k0 < PPLD; k0 += 32) {
#pragma unroll
        for (int r = 0; r < 4; r++) {
            int e = t + 256 * r; int kk = e & 31, fl = e >> 5;
            int fc = fc0 + fl;
            As[fl][kk] = (fc < NFC) ? g_Pp[fc * PPLD + k0 + kk] : 0.f;
        }
#pragma unroll
        for (int r = 0; r < 4; r++) {
            int e = t + 256 * r; int kk = e & 31, ml = e >> 5;
            int m = m0 + ml;
            Bs[ml][kk] = (m < NM) ? g_W2T[m * PPLD + k0 + kk] : 0.f;
        }
        __syncthreads();
#pragma unroll
        for (int kk = 0; kk < 32; kk++) {
            float a0 = As[ty][kk], a1 = As[ty + 16][kk];
            float b0 = Bs[tx][kk], b1 = Bs[tx + 16][kk];
            acc[0][0] += a0 * b0; acc[0][1] += a0 * b1;
            acc[1][0] += a1 * b0; acc[1][1] += a1 * b1;
        }
        __syncthreads();
    }
#pragma unroll
    for (int i = 0; i < 2; i++) {
        int fc = fc0 + ty + 16 * i;
        if (fc >= NFC) continue;
        int f = fc / 3, c = fc - 3 * f;
#pragma unroll
        for (int jj = 0; jj < 2; jj++) {
            int m = m0 + tx + 16 * jj;
            if (m < NM) g_D[f * NNP + m * 3 + c] = acc[i][jj];
        }
    }
}

// ---------------- fused: pose features + chain + GEMM + epilogue ----------------
// smem float layout (19632 floats = 78528 B):
//   Ps  [0 .. 16128)        (aliased early by ths[0..720) and pfs[720..2880))
//   As  [16128 .. 19200)    16 batches x 192
//   Ms  [19200 .. 19536)
//   Ts  [19536 .. 19584)
//   Jks [19584 .. 19632)
#define SMEM_BYTES 78528
__global__ __launch_bounds__(256, 2)
void k_fused(const float* __restrict__ theta, const float* __restrict__ dq,
             const float* __restrict__ iq, const float* __restrict__ tr,
             float* __restrict__ out) {
    extern __shared__ float sm[];
    float* Ps  = sm;
    float* Asm = sm + 16128;
    float* Ms  = sm + 19200;
    float* Ts  = sm + 19536;
    float* Jks = sm + 19584;
    float* ths = sm;          // alias (dead before Ps writes)
    float* pfs = sm + 720;    // alias (dead before Ps writes); 8B aligned
    u64*  pf64 = (u64*)pfs;

    int t = threadIdx.x;
    int b0 = blockIdx.x * 16;

    // ---- stage: theta slab, M, trans, Jk ----
    for (int i = t; i < 720; i += 256) ths[i] = theta[b0 * 45 + i];
    for (int i = t; i < NM; i += 256) Ms[i] = g_M[i];
    if (t < 48) Ts[t] = tr[b0 * 3 + t];
    if (t >= 64 && t < 112) Jks[t - 64] = g_Jk[t - 64];
    __syncthreads();

    // ---- pose features: 240 threads, one per (batch, rot) ----
    if (t < 240) {
        int bl = t / 15, i = t - bl * 15;
        const float* th = ths + bl * 45 + 3 * i;
        float tx = th[0], ty = th[1], tz = th[2];
        float ax = tx + 1e-8f, ay = ty + 1e-8f, az = tz + 1e-8f;
        float angle = sqrtf(ax * ax + ay * ay + az * az);
        float inv = 1.0f / angle;
        float nx = tx * inv, ny = ty * inv, nz = tz * inv;
        float sh, ch;
        sincosf(0.5f * angle, &sh, &ch);
        float qw = ch, qx = sh * nx, qy = sh * ny, qz = sh * nz;
        float qn = rsqrtf(qw * qw + qx * qx + qy * qy + qz * qz);
        qw *= qn; qx *= qn; qy *= qn; qz *= qn;
        float w2 = qw * qw, x2 = qx * qx, y2 = qy * qy, z2 = qz * qz;
        float wx = qw * qx, wy = qw * qy, wz = qw * qz;
        float xy = qx * qy, xz = qx * qz, yz = qy * qz;
        float o[9];
        o[0] = w2 + x2 - y2 - z2 - 1.0f;
        o[1] = 2.f * (xy - wz);
        o[2] = 2.f * (wy + xz);
        o[3] = 2.f * (wz + xy);
        o[4] = w2 - x2 + y2 - z2 - 1.0f;
        o[5] = 2.f * (yz - wx);
        o[6] = 2.f * (xz - wy);
        o[7] = 2.f * (wx + yz);
        o[8] = w2 - x2 - y2 + z2 - 1.0f;
#pragma unroll
        for (int e = 0; e < 9; e++) pfs[(9 * i + e) * 16 + bl] = o[e];
    }
    __syncthreads();

    // ---- kinematic chain: 48 threads, one per (batch, row k) ----
    if (t < 48) {
        int bl = t / 3, k = t - bl * 3;
        int b = b0 + bl;
        // root rotation (each thread computes full R, keeps its row)
        float w1 = dq[b * 4 + 0], x1 = dq[b * 4 + 1], y1 = dq[b * 4 + 2], z1 = dq[b * 4 + 3];
        float w2q = iq[0], x2q = iq[1], y2q = iq[2], z2q = iq[3];
        float qw = w1 * w2q - x1 * x2q - y1 * y2q - z1 * z2q;
        float qx = w1 * x2q + x1 * w2q + y1 * z2q - z1 * y2q;
        float qy = w1 * y2q - x1 * z2q + y1 * w2q + z1 * x2q;
        float qz = w1 * z2q + x1 * y2q - y1 * x2q + z1 * w2q;
        float qn = rsqrtf(qw * qw + qx * qx + qy * qy + qz * qz);
        qw *= qn; qx *= qn; qy *= qn; qz *= qn;
        float W2_ = qw * qw, X2 = qx * qx, Y2 = qy * qy, Z2 = qz * qz;
        float WX = qw * qx, WY = qw * qy, WZ = qw * qz;
        float XY = qx * qy, XZ = qx * qz, YZ = qy * qz;
        float R[9];
        R[0] = W2_ + X2 - Y2 - Z2; R[1] = 2.f * (XY - WZ);    R[2] = 2.f * (WY + XZ);
        R[3] = 2.f * (WZ + XY);    R[4] = W2_ - X2 + Y2 - Z2; R[5] = 2.f * (YZ - WX);
        R[6] = 2.f * (XZ - WY);    R[7] = 2.f * (WX + YZ);    R[8] = W2_ - X2 - Y2 + Z2;

        float rr0 = R[3 * k + 0], rr1 = R[3 * k + 1], rr2 = R[3 * k + 2];
        float rt = Jks[k];
        float* Ao = Asm + bl * 192;
        {
            float jx = Jks[0], jy = Jks[1], jz = Jks[2];
            Ao[k * 3 + 0] = rr0; Ao[k * 3 + 1] = rr1; Ao[k * 3 + 2] = rr2;
            Ao[9 + k] = rt - (rr0 * jx + rr1 * jy + rr2 * jz);
        }
#pragma unroll
        for (int chn = 0; chn < 5; chn++) {
            float cr0 = rr0, cr1 = rr1, cr2 = rr2, ct = rt;
#pragma unroll
            for (int s = 0; s < 3; s++) {
                int i = chn * 3 + 1 + s;
                int p = (s == 0) ? 0 : (i - 1);
                float Ri[9];
#pragma unroll
                for (int e = 0; e < 9; e++)
                    Ri[e] = pfs[(9 * (i - 1) + e) * 16 + bl]
                          + ((e == 0 || e == 4 || e == 8) ? 1.0f : 0.0f);
                float rx = Jks[3 * i + 0] - Jks[3 * p + 0];
                float ry = Jks[3 * i + 1] - Jks[3 * p + 1];
                float rz = Jks[3 * i + 2] - Jks[3 * p + 2];
                float n0 = cr0 * Ri[0] + cr1 * Ri[3] + cr2 * Ri[6];
                float n1 = cr0 * Ri[1] + cr1 * Ri[4] + cr2 * Ri[7];
                float n2 = cr0 * Ri[2] + cr1 * Ri[5] + cr2 * Ri[8];
                float nt = cr0 * rx + cr1 * ry + cr2 * rz + ct;
                float jx = Jks[3 * i + 0], jy = Jks[3 * i + 1], jz = Jks[3 * i + 2];
                float* Aoi = Ao + i * 12;
                Aoi[k * 3 + 0] = n0; Aoi[k * 3 + 1] = n1; Aoi[k * 3 + 2] = n2;
                Aoi[9 + k] = nt - (n0 * jx + n1 * jy + n2 * jz);
                cr0 = n0; cr1 = n1; cr2 = n2; ct = nt;
            }
        }
    }

    // ---- main GEMM: thread owns n = 4t..4t+3, 8 batch-pairs ----
    float4 c0 = *(const float4*)&g_C0[4 * t];
    u64 acc[4][8];
    {
        u64 cc0 = pk2(c0.x, c0.x), cc1 = pk2(c0.y, c0.y),
            cc2 = pk2(c0.z, c0.z), cc3 = pk2(c0.w, c0.w);
#pragma unroll
        for (int bp = 0; bp < 8; bp++) {
            acc[0][bp] = cc0; acc[1][bp] = cc1; acc[2][bp] = cc2; acc[3][bp] = cc3;
        }
    }
    float4 dc = *(const float4*)&g_D[4 * t];
    for (int f = 0; f < NF; f++) {
        float4 dn;
        if (f + 1 < NF) dn = *(const float4*)&g_D[(f + 1) * NNP + 4 * t];
        u64 d0 = pk2(dc.x, dc.x), d1 = pk2(dc.y, dc.y),
            d2 = pk2(dc.z, dc.z), d3 = pk2(dc.w, dc.w);
#pragma unroll
        for (int bp = 0; bp < 8; bp++) {
            u64 p = pf64[f * 8 + bp];
            acc[0][bp] = fma2(d0, p, acc[0][bp]);
            acc[1][bp] = fma2(d1, p, acc[1][bp]);
            acc[2][bp] = fma2(d2, p, acc[2][bp]);
            acc[3][bp] = fma2(d3, p, acc[3][bp]);
        }
        dc = dn;
    }
    __syncthreads();   // all loops done; pfs/ths dead

    // ---- spill P to smem ----
#pragma unroll
    for (int k = 0; k < 4; k++) {
        int n = 4 * t + k;
        if (n < NN) {
#pragma unroll
            for (int bp = 0; bp < 8; bp++) {
                float x, y; upk2(acc[k][bp], x, y);
                Ps[(2 * bp) * NN + n] = x;
                Ps[(2 * bp + 1) * NN + n] = y;
            }
        }
    }
    __syncthreads();

    // ---- epilogue: joints = A ∘ P + M*t + trans ----
    for (int idx = t; idx < 1008; idx += 256) {
        int bl = idx / 63;
        int r = idx - bl * 63;
        int jo = r / 3;
        int k = r - jo * 3;
        const float* Ab = Asm + bl * 192;
        const float* Pb = Ps + bl * NN;
        float s = Ts[bl * 3 + k];
#pragma unroll
        for (int j = 0; j < 16; j++) {
            int rb = j * 12 + k * 3;
            int pb = (jo * 16 + j) * 3;
            s += Ab[rb] * Pb[pb] + Ab[rb + 1] * Pb[pb + 1] + Ab[rb + 2] * Pb[pb + 2]
               + Ms[jo * 16 + j] * Ab[j * 12 + 9 + k];
        }
        out[(b0 + bl) * 63 + jo * 3 + k] = s;
    }
}

// ---------------- launcher ----------------
extern "C" void kernel_launch(void* const* d_in, const int* in_sizes, int n_in,
                              void* d_out, int out_size) {
    const float* theta = (const float*)d_in[0];
    const float* dq    = (const float*)d_in[1];
    const float* us    = (const float*)d_in[2];
    const float* iq    = (const float*)d_in[3];
    const float* tr    = (const float*)d_in[4];
    const float* vt    = (const float*)d_in[5];
    const float* sd    = (const float*)d_in[6];
    const float* Jr    = (const float*)d_in[7];
    const float* pd    = (const float*)d_in[8];
    const float* wg    = (const float*)d_in[9];
    float* out = (float*)d_out;

    cudaFuncSetAttribute(k_fused, cudaFuncAttributeMaxDynamicSharedMemorySize, SMEM_BYTES);

    k_pre1<<<25, 256>>>(us, sd, vt, Jr, wg);
    k_Pp<<<(NFC * NVRT + 255) / 256, 256>>>(pd);
    k_pre2<<<NM + 63, 128>>>(Jr);
    k_D<<<dim3(11, 13), 256>>>();
    k_fused<<<BATCH / 16, 256, SMEM_BYTES>>>(theta, dq, iq, tr, out);
}

// round 4
// speedup vs baseline: 1.7851x; 1.0712x over previous
#include <cuda_runtime.h>
#include <math.h>

#define BATCH 8192
#define NVRT  778
#define NJO   21
#define NF    135
#define NM    336      /* 21*16 */
#define NN    1008     /* NM*3  */
#define NNP   1024
#define NFC   405      /* NF*3  */
#define PPLD  784
#define KSPLIT 4
#define KSEG  196      /* PPLD / KSPLIT */

// ---------------- scratch (__device__ globals; zero-init; padding never written) ----
__device__ float g_vsh[NVRT * 3];
__device__ float g_Jk[64];
__device__ float g_W2T[NM * PPLD];       // [m][v], rows padded to 784 (tail stays 0)
__device__ float g_Pp[NFC * PPLD];       // [fc][v], tail stays 0
__device__ float g_M[NM];
__device__ float g_C0[NNP];              // [1008..1024) stays 0
__device__ float g_Dp[KSPLIT * NF * NNP];// split-K partials (padding never written -> 0)
__device__ float g_D[NF * NNP];          // combined (padding written 0 by reduce)

// ---------------- f32x2 helpers ----------------
typedef unsigned long long u64;
__device__ __forceinline__ u64 pk2(float x, float y) {
    u64 r; asm("mov.b64 %0, {%1, %2};" : "=l"(r) : "f"(x), "f"(y)); return r;
}
__device__ __forceinline__ void upk2(u64 v, float& x, float& y) {
    asm("mov.b64 {%0, %1}, %2;" : "=f"(x), "=f"(y) : "l"(v));
}
__device__ __forceinline__ u64 fma2(u64 a, u64 b, u64 c) {
    u64 d; asm("fma.rn.f32x2 %0, %1, %2, %3;" : "=l"(d) : "l"(a), "l"(b), "l"(c)); return d;
}

// ================ stage A: vsh + W2T (25 blocks)  ||  Pp transpose (1231 blocks) ========
#define PP_BLKS ((NFC * NVRT + 255) / 256)
__global__ void k_A(const float* __restrict__ us, const float* __restrict__ sd,
                    const float* __restrict__ vt, const float* __restrict__ Jr,
                    const float* __restrict__ wg, const float* __restrict__ pd) {
    int t = threadIdx.x;
    if (blockIdx.x < 25) {
        __shared__ float jrs[32 * 21];
        __shared__ float wgs[32 * 17];
        int v0 = blockIdx.x * 32;
        int nv = NVRT - v0; if (nv > 32) nv = 32;
        for (int i = t; i < nv * 21; i += 256) jrs[i] = Jr[v0 * 21 + i];
        for (int i = t; i < nv * 16; i += 256) {
            int vl = i >> 4, j = i & 15;
            wgs[vl * 17 + j] = wg[(v0 + vl) * 16 + j];
        }
        for (int i = t; i < nv * 3; i += 256) {
            int g = v0 * 3 + i;
            float s = vt[g];
#pragma unroll
            for (int q = 0; q < 10; q++) s += us[q] * sd[q * 2334 + g];
            g_vsh[g] = s;
        }
        __syncthreads();
        for (int i = t; i < NM * 32; i += 256) {
            int vl = i & 31, m = i >> 5;
            int v = v0 + vl;
            if (v < NVRT)
                g_W2T[m * PPLD + v] = jrs[vl * 21 + (m >> 4)] * wgs[vl * 17 + (m & 15)];
        }
    } else {
        int idx = (blockIdx.x - 25) * 256 + t;
        if (idx < NFC * NVRT) {
            int fc = idx / NVRT, v = idx - fc * NVRT;
            int f = fc / 3, c = fc - 3 * f;
            g_Pp[fc * PPLD + v] = pd[f * 2334 + 3 * v + c];
        }
    }
}

// ================ stage B: Jk/M/C0 (399 blocks)  ||  D split-K partials (572 blocks) ====
__global__ void k_B(const float* __restrict__ Jr) {
    int t = threadIdx.x;
    int blk = blockIdx.x;
    if (blk < NM + 63) {
        // ---- pre2: M, C0, Jk ----
        __shared__ float vs[NVRT * 3];
        __shared__ float red[4][256];
        for (int i = t; i < NVRT * 3; i += 256) vs[i] = g_vsh[i];
        __syncthreads();
        if (blk < NM) {
            int m = blk;
            float sm = 0.f, s0 = 0.f, s1 = 0.f, s2 = 0.f;
            for (int v = t; v < NVRT; v += 256) {
                float w = g_W2T[m * PPLD + v];
                sm += w;
                s0 += w * vs[v * 3 + 0];
                s1 += w * vs[v * 3 + 1];
                s2 += w * vs[v * 3 + 2];
            }
            red[0][t] = sm; red[1][t] = s0; red[2][t] = s1; red[3][t] = s2;
            __syncthreads();
            for (int o = 128; o > 0; o >>= 1) {
                if (t < o) {
                    red[0][t] += red[0][t + o]; red[1][t] += red[1][t + o];
                    red[2][t] += red[2][t + o]; red[3][t] += red[3][t + o];
                }
                __syncthreads();
            }
            if (t == 0) {
                g_M[m] = red[0][0];
                g_C0[m * 3 + 0] = red[1][0];
                g_C0[m * 3 + 1] = red[2][0];
                g_C0[m * 3 + 2] = red[3][0];
            }
        } else {
            int idx = blk - NM;
            int j = idx / 3, c = idx - 3 * j;
            float s = 0.f;
            for (int v = t; v < NVRT; v += 256) s += vs[v * 3 + c] * Jr[v * 21 + j];
            red[0][t] = s; __syncthreads();
            for (int o = 128; o > 0; o >>= 1) {
                if (t < o) red[0][t] += red[0][t + o];
                __syncthreads();
            }
            if (t == 0) g_Jk[j * 3 + c] = red[0][0];
        }
    } else {
        // ---- D partial: D_ks[fc][m] = sum_{v in seg} Pp[fc][v] * W2T[m][v] ----
        __shared__ float As[32][33];
        __shared__ float Bs[32][33];
        int b2 = blk - (NM + 63);
        int ks = b2 / 143;
        int rem = b2 - ks * 143;
        int m0 = (rem % 11) * 32;
        int fc0 = (rem / 11) * 32;
        int kbase = ks * KSEG, kend = kbase + KSEG;
        int tx = t & 15, ty = t >> 4;
        float acc[2][2] = {};
        for (int k0 = kbase; k0 < kend; k0 += 32) {
#pragma unroll
            for (int r = 0; r < 4; r++) {
                int e = t + 256 * r; int kk = e & 31, fl = e >> 5;
                int fc = fc0 + fl, k = k0 + kk;
                As[fl][kk] = (fc < NFC && k < kend) ? g_Pp[fc * PPLD + k] : 0.f;
            }
#pragma unroll
            for (int r = 0; r < 4; r++) {
                int e = t + 256 * r; int kk = e & 31, ml = e >> 5;
                int m = m0 + ml, k = k0 + kk;
                Bs[ml][kk] = (m < NM && k < kend) ? g_W2T[m * PPLD + k] : 0.f;
            }
            __syncthreads();
#pragma unroll
            for (int kk = 0; kk < 32; kk++) {
                float a0 = As[ty][kk], a1 = As[ty + 16][kk];
                float b0 = Bs[tx][kk], b1 = Bs[tx + 16][kk];
                acc[0][0] += a0 * b0; acc[0][1] += a0 * b1;
                acc[1][0] += a1 * b0; acc[1][1] += a1 * b1;
            }
            __syncthreads();
        }
#pragma unroll
        for (int i = 0; i < 2; i++) {
            int fc = fc0 + ty + 16 * i;
            if (fc >= NFC) continue;
            int f = fc / 3, c = fc - 3 * f;
#pragma unroll
            for (int jj = 0; jj < 2; jj++) {
                int m = m0 + tx + 16 * jj;
                if (m < NM) g_Dp[(ks * NF + f) * NNP + m * 3 + c] = acc[i][jj];
            }
        }
    }
}

// ================ stage C: combine split-K partials ================
__global__ void k_red() {
    int idx = blockIdx.x * 256 + threadIdx.x;   // grid covers NF*NNP exactly
    const int S = NF * NNP;
    g_D[idx] = (g_Dp[idx] + g_Dp[S + idx]) + (g_Dp[2 * S + idx] + g_Dp[3 * S + idx]);
}

// ================ fused: pose features + chain + GEMM + epilogue ================
// 512 threads, 32 batches (16 pairs) per block. smem floats:
//   Ps  [0 .. 32256)      32 x 1008   (aliased early: ths [0..1440), pfs [1440..5760))
//   Asm [32256 .. 38400)  32 x 192
//   Ms  [38400 .. 38736)
//   Ts  [38736 .. 38832)
//   Jks [38832 .. 38880)
#define SMEM_BYTES (38880 * 4)
__global__ __launch_bounds__(512, 1)
void k_fused(const float* __restrict__ theta, const float* __restrict__ dq,
             const float* __restrict__ iq, const float* __restrict__ tr,
             float* __restrict__ out) {
    extern __shared__ float sm[];
    float* Ps  = sm;
    float* Asm = sm + 32256;
    float* Ms  = sm + 38400;
    float* Ts  = sm + 38736;
    float* Jks = sm + 38832;
    float* ths = sm;            // alias (dead before Ps writes)
    float* pfs = sm + 1440;     // alias (dead before Ps writes); 16B aligned
    u64*  pf64 = (u64*)pfs;     // [f][bp], bp = pair index 0..15

    int t = threadIdx.x;
    int b0 = blockIdx.x * 32;

    // ---- stage inputs ----
    for (int i = t; i < 1440; i += 512) ths[i] = theta[b0 * 45 + i];
    if (t >= 512 - 96 && t < 512 - 96 + 48) { int i = t - (512 - 96); Jks[i] = g_Jk[i]; }
    for (int i = t; i < NM; i += 512) Ms[i] = g_M[i];
    if (t < 96) Ts[t] = tr[b0 * 3 + t];
    __syncthreads();

    // ---- pose features: 480 threads, one per (batch, rot) ----
    if (t < 480) {
        int bl = t / 15, i = t - bl * 15;
        const float* th = ths + bl * 45 + 3 * i;
        float tx = th[0], ty = th[1], tz = th[2];
        float ax = tx + 1e-8f, ay = ty + 1e-8f, az = tz + 1e-8f;
        float angle = sqrtf(ax * ax + ay * ay + az * az);
        float inv = 1.0f / angle;
        float nx = tx * inv, ny = ty * inv, nz = tz * inv;
        float sh, ch;
        sincosf(0.5f * angle, &sh, &ch);
        float qw = ch, qx = sh * nx, qy = sh * ny, qz = sh * nz;
        float qn = rsqrtf(qw * qw + qx * qx + qy * qy + qz * qz);
        qw *= qn; qx *= qn; qy *= qn; qz *= qn;
        float w2 = qw * qw, x2 = qx * qx, y2 = qy * qy, z2 = qz * qz;
        float wx = qw * qx, wy = qw * qy, wz = qw * qz;
        float xy = qx * qy, xz = qx * qz, yz = qy * qz;
        float o[9];
        o[0] = w2 + x2 - y2 - z2 - 1.0f;
        o[1] = 2.f * (xy - wz);
        o[2] = 2.f * (wy + xz);
        o[3] = 2.f * (wz + xy);
        o[4] = w2 - x2 + y2 - z2 - 1.0f;
        o[5] = 2.f * (yz - wx);
        o[6] = 2.f * (xz - wy);
        o[7] = 2.f * (wx + yz);
        o[8] = w2 - x2 - y2 + z2 - 1.0f;
        int bp = bl >> 1, lo = bl & 1;
#pragma unroll
        for (int e = 0; e < 9; e++)
            pfs[((9 * i + e) * 16 + bp) * 2 + lo] = o[e];
    }
    __syncthreads();

    // ---- kinematic chain: 96 threads, one per (batch, row k) ----
    if (t < 96) {
        int bl = t / 3, k = t - bl * 3;
        int b = b0 + bl;
        float w1 = dq[b * 4 + 0], x1 = dq[b * 4 + 1], y1 = dq[b * 4 + 2], z1 = dq[b * 4 + 3];
        float w2q = iq[0], x2q = iq[1], y2q = iq[2], z2q = iq[3];
        float qw = w1 * w2q - x1 * x2q - y1 * y2q - z1 * z2q;
        float qx = w1 * x2q + x1 * w2q + y1 * z2q - z1 * y2q;
        float qy = w1 * y2q - x1 * z2q + y1 * w2q + z1 * x2q;
        float qz = w1 * z2q + x1 * y2q - y1 * x2q + z1 * w2q;
        float qn = rsqrtf(qw * qw + qx * qx + qy * qy + qz * qz);
        qw *= qn; qx *= qn; qy *= qn; qz *= qn;
        float W2_ = qw * qw, X2 = qx * qx, Y2 = qy * qy, Z2 = qz * qz;
        float WX = qw * qx, WY = qw * qy, WZ = qw * qz;
        float XY = qx * qy, XZ = qx * qz, YZ = qy * qz;
        float R[9];
        R[0] = W2_ + X2 - Y2 - Z2; R[1] = 2.f * (XY - WZ);    R[2] = 2.f * (WY + XZ);
        R[3] = 2.f * (WZ + XY);    R[4] = W2_ - X2 + Y2 - Z2; R[5] = 2.f * (YZ - WX);
        R[6] = 2.f * (XZ - WY);    R[7] = 2.f * (WX + YZ);    R[8] = W2_ - X2 - Y2 + Z2;

        float rr0 = R[3 * k + 0], rr1 = R[3 * k + 1], rr2 = R[3 * k + 2];
        float rt = Jks[k];
        float* Ao = Asm + bl * 192;
        {
            float jx = Jks[0], jy = Jks[1], jz = Jks[2];
            Ao[k * 3 + 0] = rr0; Ao[k * 3 + 1] = rr1; Ao[k * 3 + 2] = rr2;
            Ao[9 + k] = rt - (rr0 * jx + rr1 * jy + rr2 * jz);
        }
        int bp = bl >> 1, lo = bl & 1;
#pragma unroll
        for (int chn = 0; chn < 5; chn++) {
            float cr0 = rr0, cr1 = rr1, cr2 = rr2, ct = rt;
#pragma unroll
            for (int s = 0; s < 3; s++) {
                int i = chn * 3 + 1 + s;
                int p = (s == 0) ? 0 : (i - 1);
                float Ri[9];
#pragma unroll
                for (int e = 0; e < 9; e++)
                    Ri[e] = pfs[((9 * (i - 1) + e) * 16 + bp) * 2 + lo]
                          + ((e == 0 || e == 4 || e == 8) ? 1.0f : 0.0f);
                float rx = Jks[3 * i + 0] - Jks[3 * p + 0];
                float ry = Jks[3 * i + 1] - Jks[3 * p + 1];
                float rz = Jks[3 * i + 2] - Jks[3 * p + 2];
                float n0 = cr0 * Ri[0] + cr1 * Ri[3] + cr2 * Ri[6];
                float n1 = cr0 * Ri[1] + cr1 * Ri[4] + cr2 * Ri[7];
                float n2 = cr0 * Ri[2] + cr1 * Ri[5] + cr2 * Ri[8];
                float nt = cr0 * rx + cr1 * ry + cr2 * rz + ct;
                float jx = Jks[3 * i + 0], jy = Jks[3 * i + 1], jz = Jks[3 * i + 2];
                float* Aoi = Ao + i * 12;
                Aoi[k * 3 + 0] = n0; Aoi[k * 3 + 1] = n1; Aoi[k * 3 + 2] = n2;
                Aoi[9 + k] = nt - (n0 * jx + n1 * jy + n2 * jz);
                cr0 = n0; cr1 = n1; cr2 = n2; ct = nt;
            }
        }
    }

    // ---- main GEMM: thread owns n = {2t, 2t+1}, 16 batch-pairs ----
    float2 c0 = *(const float2*)&g_C0[2 * t];
    u64 acc[2][16];
    {
        u64 cc0 = pk2(c0.x, c0.x), cc1 = pk2(c0.y, c0.y);
#pragma unroll
        for (int bp = 0; bp < 16; bp++) { acc[0][bp] = cc0; acc[1][bp] = cc1; }
    }
    float2 dc = *(const float2*)&g_D[2 * t];
    for (int f = 0; f < NF; f++) {
        float2 dn;
        if (f + 1 < NF) dn = *(const float2*)&g_D[(f + 1) * NNP + 2 * t];
        u64 d0 = pk2(dc.x, dc.x), d1 = pk2(dc.y, dc.y);
        const u64* prow = pf64 + f * 16;
#pragma unroll
        for (int bq = 0; bq < 8; bq++) {
            u64 p0, p1;
            asm("ld.shared.v2.u64 {%0, %1}, [%2];"
                : "=l"(p0), "=l"(p1)
                : "l"(__cvta_generic_to_shared(prow + 2 * bq)));
            acc[0][2 * bq]     = fma2(d0, p0, acc[0][2 * bq]);
            acc[1][2 * bq]     = fma2(d1, p0, acc[1][2 * bq]);
            acc[0][2 * bq + 1] = fma2(d0, p1, acc[0][2 * bq + 1]);
            acc[1][2 * bq + 1] = fma2(d1, p1, acc[1][2 * bq + 1]);
        }
        dc = dn;
    }
    __syncthreads();   // pfs/ths now dead

    // ---- spill P to smem ----
#pragma unroll
    for (int k = 0; k < 2; k++) {
        int n = 2 * t + k;
        if (n < NN) {
#pragma unroll
            for (int bp = 0; bp < 16; bp++) {
                float x, y; upk2(acc[k][bp], x, y);
                Ps[(2 * bp) * NN + n] = x;
                Ps[(2 * bp + 1) * NN + n] = y;
            }
        }
    }
    __syncthreads();

    // ---- epilogue: joints = A ∘ P + M*t + trans ----
    for (int idx = t; idx < 32 * 63; idx += 512) {
        int bl = idx / 63;
        int r = idx - bl * 63;
        int jo = r / 3;
        int k = r - jo * 3;
        const float* Ab = Asm + bl * 192;
        const float* Pb = Ps + bl * NN;
        float s = Ts[bl * 3 + k];
#pragma unroll
        for (int j = 0; j < 16; j++) {
            int rb = j * 12 + k * 3;
            int pb = (jo * 16 + j) * 3;
            s += Ab[rb] * Pb[pb] + Ab[rb + 1] * Pb[pb + 1] + Ab[rb + 2] * Pb[pb + 2]
               + Ms[jo * 16 + j] * Ab[j * 12 + 9 + k];
        }
        out[(b0 + bl) * 63 + jo * 3 + k] = s;
    }
}

// ---------------- launcher ----------------
extern "C" void kernel_launch(void* const* d_in, const int* in_sizes, int n_in,
                              void* d_out, int out_size) {
    const float* theta = (const float*)d_in[0];
    const float* dq    = (const float*)d_in[1];
    const float* us    = (const float*)d_in[2];
    const float* iq    = (const float*)d_in[3];
    const float* tr    = (const float*)d_in[4];
    const float* vt    = (const float*)d_in[5];
    const float* sd    = (const float*)d_in[6];
    const float* Jr    = (const float*)d_in[7];
    const float* pd    = (const float*)d_in[8];
    const float* wg    = (const float*)d_in[9];
    float* out = (float*)d_out;

    cudaFuncSetAttribute(k_fused, cudaFuncAttributeMaxDynamicSharedMemorySize, SMEM_BYTES);

    k_A<<<25 + PP_BLKS, 256>>>(us, sd, vt, Jr, wg, pd);
    k_B<<<NM + 63 + 143 * KSPLIT, 256>>>(Jr);
    k_red<<<(NF * NNP) / 256, 256>>>();
    k_fused<<<BATCH / 32, 512, SMEM_BYTES>>>(theta, dq, iq, tr, out);
}